// round 10
// baseline (speedup 1.0000x reference)
#include <cuda_runtime.h>

#define Kn 6000
#define Np 3000
#define Mp 3000
#define F 256
#define H 4
#define HID 64
#define MAXNB 32
#define R2 0.0025f
#define SLOPE 0.2f

#define CELLS 20
#define NCELL (CELLS * CELLS * CELLS)
#define CSINV 19.8019801980198f   /* 1 / 0.0505 ; cell > max accepted pair dist */

// ---- device scratch (no dynamic allocation allowed) ----
__device__ float4 g_pts[Kn];
__device__ int    g_cellid[Kn];
__device__ int    g_cellcnt[NCELL];
__device__ int    g_cellstart[NCELL + 1];
__device__ int    g_cellpts[Kn];
__device__ int    g_nbr[Kn * MAXNB];
__device__ int    g_cnt[Kn];
__device__ float  g_h[Kn * F];
__device__ float  g_x[Kn * F];
__device__ float  g_es[Kn * H];
__device__ float  g_ed[Kn * H];

// ---- packed f32x2 helpers (bit-identical rn fp32 per lane, 2x FMA pipe) ----
__device__ __forceinline__ unsigned long long pack2(float lo, float hi) {
    unsigned long long r;
    asm("mov.b64 %0, {%1, %2};" : "=l"(r) : "f"(lo), "f"(hi));
    return r;
}
__device__ __forceinline__ void unpack2(unsigned long long v, float& lo, float& hi) {
    asm("mov.b64 {%0, %1}, %2;" : "=f"(lo), "=f"(hi) : "l"(v));
}
__device__ __forceinline__ void ffma2(unsigned long long& acc,
                                      unsigned long long a, unsigned long long b) {
    asm("fma.rn.f32x2 %0, %1, %2, %0;" : "+l"(acc) : "l"(a), "l"(b));
}

// ---------------------------------------------------------------------------
// 1. pack points {x,y,z,|p|^2}, compute cell id, count per cell
//    (g_cellcnt zeroed by a captured cudaMemsetAsync before this launch)
// ---------------------------------------------------------------------------
__global__ void build_pts(const float* __restrict__ pos,
                          const float* __restrict__ pnm) {
    int i = blockIdx.x * blockDim.x + threadIdx.x;
    if (i >= Kn) return;
    float x, y, z;
    if (i < Np) { x = pos[i];     y = pos[Np + i];  z = pos[2 * Np + i]; }
    else        { int j = i - Np; x = pnm[j];       y = pnm[Mp + j];  z = pnm[2 * Mp + j]; }
    float sq = x * x + y * y + z * z;
    g_pts[i] = make_float4(x, y, z, sq);
    int cx = min(CELLS - 1, max(0, (int)(x * CSINV)));
    int cy = min(CELLS - 1, max(0, (int)(y * CSINV)));
    int cz = min(CELLS - 1, max(0, (int)(z * CSINV)));
    int cell = (cz * CELLS + cy) * CELLS + cx;
    g_cellid[i] = cell;
    atomicAdd(&g_cellcnt[cell], 1);
}

// ---------------------------------------------------------------------------
// 2. fused exclusive scan (shfl-based, 2 barriers) + scatter.
//    One block, 1024 threads; fill cursors live in shared memory.
// ---------------------------------------------------------------------------
__global__ void scan_scatter() {
    __shared__ int sfill[NCELL];   // 32 KB fill cursors
    __shared__ int wsum[32];
    int t = threadIdx.x;
    int lane = t & 31, warp = t >> 5;

    int loc[8], s = 0;
#pragma unroll
    for (int q = 0; q < 8; q++) {
        int idx = t * 8 + q;
        loc[q] = s;
        if (idx < NCELL) s += g_cellcnt[idx];
    }
    // inclusive warp scan of per-thread sums
    int incl = s;
#pragma unroll
    for (int off = 1; off < 32; off <<= 1) {
        int v = __shfl_up_sync(0xffffffffu, incl, off);
        if (lane >= off) incl += v;
    }
    if (lane == 31) wsum[warp] = incl;
    __syncthreads();
    if (warp == 0) {
        int v = wsum[lane];
        int w = v;
#pragma unroll
        for (int off = 1; off < 32; off <<= 1) {
            int u = __shfl_up_sync(0xffffffffu, w, off);
            if (lane >= off) w += u;
        }
        wsum[lane] = w;
    }
    __syncthreads();
    int base = ((warp > 0) ? wsum[warp - 1] : 0) + incl - s;  // exclusive thread base
#pragma unroll
    for (int q = 0; q < 8; q++) {
        int idx = t * 8 + q;
        if (idx < NCELL) {
            int st = base + loc[q];
            g_cellstart[idx] = st;
            sfill[idx] = st;
        }
    }
    if (t == 1023) g_cellstart[NCELL] = wsum[31];
    __syncthreads();

    // scatter (~6 points per thread); order randomized but nbr rank-sort fixes it
    for (int i = t; i < Kn; i += 1024) {
        int c = g_cellid[i];
        int p = atomicAdd(&sfill[c], 1);
        g_cellpts[p] = i;
    }
}

// ---------------------------------------------------------------------------
// 3. warp-per-node radius search. Lanes scan candidates in parallel;
//    3 x-adjacent cells are contiguous in g_cellpts -> 9 spans per node.
//    Ballot-compacted hits, then rank-sorted ascending (indices unique)
//    -> identical edge list + order as the serial version.
// ---------------------------------------------------------------------------
__global__ void nbr_search() {
    __shared__ int buf[4][MAXNB];
    int wslot = threadIdx.x >> 5;
    int lane  = threadIdx.x & 31;
    int i     = (blockIdx.x * blockDim.x + threadIdx.x) >> 5;
    if (i >= Kn) return;
    float4 pi = g_pts[i];
    int cx = min(CELLS - 1, max(0, (int)(pi.x * CSINV)));
    int cy = min(CELLS - 1, max(0, (int)(pi.y * CSINV)));
    int cz = min(CELLS - 1, max(0, (int)(pi.z * CSINV)));
    int x0 = max(cx - 1, 0), x1 = min(cx + 1, CELLS - 1);
    int* nb = buf[wslot];
    int cnt = 0;
    for (int dz = -1; dz <= 1; dz++) {
        int z = cz + dz;
        if ((unsigned)z >= CELLS) continue;
        for (int dy = -1; dy <= 1; dy++) {
            int y = cy + dy;
            if ((unsigned)y >= CELLS) continue;
            int rowbase = (z * CELLS + y) * CELLS;
            int s = g_cellstart[rowbase + x0];
            int e = g_cellstart[rowbase + x1 + 1];
            for (int t0 = s; t0 < e; t0 += 32) {
                int t = t0 + lane;
                bool ok = false;
                int j = -1;
                if (t < e) {
                    j = g_cellpts[t];
                    float4 pj = g_pts[j];
                    float dot = pi.x * pj.x + pi.y * pj.y + pi.z * pj.z;
                    float d2  = (pi.w + pj.w) - 2.0f * dot;   // identical to reference
                    ok = (d2 < R2);
                }
                unsigned m = __ballot_sync(0xffffffffu, ok);
                if (ok) {
                    int p = cnt + __popc(m & ((1u << lane) - 1u));
                    if (p < MAXNB) nb[p] = j;
                }
                cnt += __popc(m);
                if (cnt > MAXNB) cnt = MAXNB;
            }
        }
    }
    __syncwarp();
    // rank sort: indices unique -> rank = #{u < v} is a permutation
    int v = (lane < cnt) ? nb[lane] : 0x7fffffff;
    int rank = 0;
#pragma unroll
    for (int k = 0; k < 32; k++) {
        int u = __shfl_sync(0xffffffffu, v, k);
        rank += (u < v);
    }
    if (lane < cnt) g_nbr[i * MAXNB + rank] = v;
    if (lane == 0)  g_cnt[i] = cnt;
}

// ---------------------------------------------------------------------------
// 4. h1 = pts @ W1 with fused attention scores (layer 1)
// ---------------------------------------------------------------------------
__global__ void feat1(const float* __restrict__ W1,
                      const float* __restrict__ asrc,
                      const float* __restrict__ adst) {
    __shared__ float S[8], D[8];
    int i = blockIdx.x;
    int c = threadIdx.x;
    float4 p = g_pts[i];
    float v = p.x * W1[c] + p.y * W1[F + c] + p.z * W1[2 * F + c];
    g_h[i * F + c] = v;
    float s = v * asrc[c];   // asrc flattened [H*HID] == channel index
    float d = v * adst[c];
#pragma unroll
    for (int off = 16; off; off >>= 1) {
        s += __shfl_xor_sync(0xffffffffu, s, off);
        d += __shfl_xor_sync(0xffffffffu, d, off);
    }
    int w = c >> 5;
    if ((c & 31) == 0) { S[w] = s; D[w] = d; }
    __syncthreads();
    if (c < H) {
        g_es[i * H + c] = S[2 * c] + S[2 * c + 1];
        g_ed[i * H + c] = D[2 * c] + D[2 * c + 1];
    }
}

// ---------------------------------------------------------------------------
// 5. sparse GAT softmax + aggregation; warp per node.
//    FINAL: only rows [Np, Kn) are ever used -> fuse fc and skip the rest.
// ---------------------------------------------------------------------------
template<bool FINAL>
__global__ void aggregate(const float* __restrict__ bias,
                          const float* __restrict__ fw,
                          const float* __restrict__ fb,
                          float* __restrict__ out) {
    int wi   = (blockIdx.x * blockDim.x + threadIdx.x) >> 5;
    int lane = threadIdx.x & 31;
    if (wi >= (FINAL ? Mp : Kn)) return;
    int node = FINAL ? (Np + wi) : wi;
    int cnt  = g_cnt[node];

    float e[H];
    int nb = 0;
    if (lane < cnt) {
        nb = g_nbr[node * MAXNB + lane];
#pragma unroll
        for (int h = 0; h < H; h++) {
            float v = g_ed[node * H + h] + g_es[nb * H + h];
            e[h] = (v >= 0.f) ? v : SLOPE * v;
        }
    } else {
#pragma unroll
        for (int h = 0; h < H; h++) e[h] = -1e30f;
    }

    float alpha[H];
#pragma unroll
    for (int h = 0; h < H; h++) {
        float m = e[h];
#pragma unroll
        for (int off = 16; off; off >>= 1)
            m = fmaxf(m, __shfl_xor_sync(0xffffffffu, m, off));
        float a = (lane < cnt) ? expf(e[h] - m) : 0.f;
        float s = a;
#pragma unroll
        for (int off = 16; off; off >>= 1)
            s += __shfl_xor_sync(0xffffffffu, s, off);
        alpha[h] = a / s;
    }

    float acc[8] = {0.f, 0.f, 0.f, 0.f, 0.f, 0.f, 0.f, 0.f};
    for (int j = 0; j < cnt; j++) {
        int   nj = __shfl_sync(0xffffffffu, nb, j);
        float aw[H];
#pragma unroll
        for (int h = 0; h < H; h++) aw[h] = __shfl_sync(0xffffffffu, alpha[h], j);
        const float* hr = g_h + nj * F;
#pragma unroll
        for (int r = 0; r < 8; r++)
            acc[r] += aw[r >> 1] * hr[lane + 32 * r];
    }

    float f0 = 0.f, f1 = 0.f;
#pragma unroll
    for (int r = 0; r < 8; r++) {
        int c = lane + 32 * r;
        float v = acc[r] + bias[c];
        v = (v > 0.f) ? v : 0.f;
        if (!FINAL) {
            g_x[node * F + c] = v;
        } else {
            f0 += v * fw[c * 2];
            f1 += v * fw[c * 2 + 1];
        }
    }
    if (FINAL) {
#pragma unroll
        for (int off = 16; off; off >>= 1) {
            f0 += __shfl_xor_sync(0xffffffffu, f0, off);
            f1 += __shfl_xor_sync(0xffffffffu, f1, off);
        }
        if (lane == 0) {
            out[wi * 2]     = f0 + fb[0];
            out[wi * 2 + 1] = f1 + fb[1];
        }
    }
}

// ---------------------------------------------------------------------------
// 6. h2 = x1 @ W2 — BM=64 x BN=64, 128 threads, 8m x 4n per thread.
//    B stored pre-duplicated (b,b) in smem; A m-pairs via aligned 16B loads.
//    Inner loop per k: 4 LDS.128 + 16 FFMA2, zero MOVs. One head per column.
// ---------------------------------------------------------------------------
#define BM 64
#define BN 64
#define BKK 16
__global__ void __launch_bounds__(128) gemm2(const float* __restrict__ W,
                                             const float* __restrict__ asrc,
                                             const float* __restrict__ adst) {
    __shared__ __align__(16) float As[BKK][BM];                  // 4 KB, As[k][m]
    __shared__ __align__(16) unsigned long long Bsd[BKK][BN];    // 8 KB, (b,b) pairs
    int tid = threadIdx.x;
    int row0 = blockIdx.y * BM, col0 = blockIdx.x * BN;
    int tx = tid & 15, ty = tid >> 4;             // tx: n-quad, ty: m-group of 8
    unsigned long long acc[4][4];                 // acc[mpair][n]
#pragma unroll
    for (int mp = 0; mp < 4; mp++)
#pragma unroll
        for (int n = 0; n < 4; n++) acc[mp][n] = 0ull;

    for (int kk = 0; kk < F; kk += BKK) {
        // A tile: 64 rows x 16 k = 256 float4; transposed STS, conflict-free.
#pragma unroll
        for (int it = 0; it < 2; it++) {
            int idx = tid + it * 128;
            int m = idx & 63, q = idx >> 6;       // q in 0..3
            int gr = row0 + m;
            float4 v = make_float4(0.f, 0.f, 0.f, 0.f);
            if (gr < Kn) v = *(const float4*)&g_x[gr * F + kk + q * 4];
            As[q * 4 + 0][m] = v.x; As[q * 4 + 1][m] = v.y;
            As[q * 4 + 2][m] = v.z; As[q * 4 + 3][m] = v.w;
        }
        // B tile: duplicate each value into a (b,b) 64-bit word at store time.
#pragma unroll
        for (int it = 0; it < 2; it++) {
            int idx = tid + it * 128;
            int k = idx >> 4, n4 = idx & 15;
            float4 w = *(const float4*)&W[(kk + k) * F + col0 + n4 * 4];
            Bsd[k][n4 * 4 + 0] = pack2(w.x, w.x);
            Bsd[k][n4 * 4 + 1] = pack2(w.y, w.y);
            Bsd[k][n4 * 4 + 2] = pack2(w.z, w.z);
            Bsd[k][n4 * 4 + 3] = pack2(w.w, w.w);
        }
        __syncthreads();
#pragma unroll
        for (int k = 0; k < BKK; k++) {
            ulonglong2 b01 = *(const ulonglong2*)&Bsd[k][tx * 4];
            ulonglong2 b23 = *(const ulonglong2*)&Bsd[k][tx * 4 + 2];
            ulonglong2 a01 = *(const ulonglong2*)&As[k][ty * 8];      // (m0,m1),(m2,m3)
            ulonglong2 a23 = *(const ulonglong2*)&As[k][ty * 8 + 4];  // (m4,m5),(m6,m7)
            ffma2(acc[0][0], a01.x, b01.x); ffma2(acc[0][1], a01.x, b01.y);
            ffma2(acc[0][2], a01.x, b23.x); ffma2(acc[0][3], a01.x, b23.y);
            ffma2(acc[1][0], a01.y, b01.x); ffma2(acc[1][1], a01.y, b01.y);
            ffma2(acc[1][2], a01.y, b23.x); ffma2(acc[1][3], a01.y, b23.y);
            ffma2(acc[2][0], a23.x, b01.x); ffma2(acc[2][1], a23.x, b01.y);
            ffma2(acc[2][2], a23.x, b23.x); ffma2(acc[2][3], a23.x, b23.y);
            ffma2(acc[3][0], a23.y, b01.x); ffma2(acc[3][1], a23.y, b01.y);
            ffma2(acc[3][2], a23.y, b23.x); ffma2(acc[3][3], a23.y, b23.y);
        }
        __syncthreads();
    }

    // epilogue: unpack, store h2, fused es/ed for this head
    float as_[4], ad_[4];
#pragma unroll
    for (int n = 0; n < 4; n++) {
        as_[n] = asrc[col0 + tx * 4 + n];
        ad_[n] = adst[col0 + tx * 4 + n];
    }
    int hidx = col0 >> 6;
#pragma unroll
    for (int mp = 0; mp < 4; mp++) {
        float c0[4], c1[4];                       // rows 2mp, 2mp+1 (within ty group)
#pragma unroll
        for (int n = 0; n < 4; n++) unpack2(acc[mp][n], c0[n], c1[n]);
#pragma unroll
        for (int half = 0; half < 2; half++) {
            float* c = half ? c1 : c0;
            int gr = row0 + ty * 8 + mp * 2 + half;
            float s = c[0] * as_[0] + c[1] * as_[1] + c[2] * as_[2] + c[3] * as_[3];
            float d = c[0] * ad_[0] + c[1] * ad_[1] + c[2] * ad_[2] + c[3] * ad_[3];
#pragma unroll
            for (int off = 8; off; off >>= 1) {   // reduce across the 16 tx lanes
                s += __shfl_xor_sync(0xffffffffu, s, off);
                d += __shfl_xor_sync(0xffffffffu, d, off);
            }
            if (gr < Kn) {
                *(float4*)&g_h[gr * F + col0 + tx * 4] =
                    make_float4(c[0], c[1], c[2], c[3]);
                if (tx == 0) {
                    g_es[gr * H + hidx] = s;
                    g_ed[gr * H + hidx] = d;
                }
            }
        }
    }
}

// ---------------------------------------------------------------------------
extern "C" void kernel_launch(void* const* d_in, const int* in_sizes, int n_in,
                              void* d_out, int out_size) {
    const float* pos   = (const float*)d_in[0];
    const float* pnm   = (const float*)d_in[1];
    const float* W1    = (const float*)d_in[2];
    const float* asrc1 = (const float*)d_in[3];
    const float* adst1 = (const float*)d_in[4];
    const float* b1    = (const float*)d_in[5];
    const float* W2    = (const float*)d_in[6];
    const float* asrc2 = (const float*)d_in[7];
    const float* adst2 = (const float*)d_in[8];
    const float* b2    = (const float*)d_in[9];
    const float* fw    = (const float*)d_in[10];
    const float* fb    = (const float*)d_in[11];
    float* out = (float*)d_out;

    // zero the cell histogram via a captured memset node (replaces a kernel)
    void* cellcnt_ptr = nullptr;
    cudaGetSymbolAddress(&cellcnt_ptr, g_cellcnt);
    cudaMemsetAsync(cellcnt_ptr, 0, NCELL * sizeof(int));

    build_pts<<<(Kn + 255) / 256, 256>>>(pos, pnm);
    scan_scatter<<<1, 1024>>>();
    nbr_search<<<(Kn * 32 + 127) / 128, 128>>>();

    // ---- GAT layer 1 (scores fused into feat1) ----
    feat1<<<Kn, F>>>(W1, asrc1, adst1);
    aggregate<false><<<(Kn * 32 + 255) / 256, 256>>>(b1, nullptr, nullptr, nullptr);

    // ---- GAT layer 2 (scores fused into gemm2 epilogue) ----
    gemm2<<<dim3(F / BN, (Kn + BM - 1) / BM), 128>>>(W2, asrc2, adst2);
    aggregate<true><<<(Mp * 32 + 255) / 256, 256>>>(b2, fw, fb, out);
}

// round 11
// speedup vs baseline: 1.1995x; 1.1995x over previous
#include <cuda_runtime.h>

#define Kn 6000
#define Np 3000
#define Mp 3000
#define F 256
#define H 4
#define HID 64
#define MAXNB 32
#define R2 0.0025f
#define SLOPE 0.2f

#define CELLS 20
#define NCELL (CELLS * CELLS * CELLS)
#define CSINV 19.8019801980198f   /* 1 / 0.0505 ; cell > max accepted pair dist */

// ---- device scratch (no dynamic allocation allowed) ----
__device__ float4 g_pts[Kn];
__device__ int    g_cellid[Kn];
__device__ int    g_cellcnt[NCELL];
__device__ int    g_cellstart[NCELL + 1];
__device__ int    g_cellpts[Kn];
__device__ int    g_nbr[Kn * MAXNB];
__device__ int    g_cnt[Kn];
__device__ float  g_h[Kn * F];
__device__ float  g_x[Kn * F];
__device__ float  g_es[Kn * H];
__device__ float  g_ed[Kn * H];

// ---- packed f32x2 helpers (bit-identical rn fp32 per lane, 2x FMA pipe) ----
__device__ __forceinline__ unsigned long long pack2(float lo, float hi) {
    unsigned long long r;
    asm("mov.b64 %0, {%1, %2};" : "=l"(r) : "f"(lo), "f"(hi));
    return r;
}
__device__ __forceinline__ void unpack2(unsigned long long v, float& lo, float& hi) {
    asm("mov.b64 {%0, %1}, %2;" : "=f"(lo), "=f"(hi) : "l"(v));
}
__device__ __forceinline__ void ffma2(unsigned long long& acc,
                                      unsigned long long a, unsigned long long b) {
    asm("fma.rn.f32x2 %0, %1, %2, %0;" : "+l"(acc) : "l"(a), "l"(b));
}

// ---------------------------------------------------------------------------
// 1. pack points {x,y,z,|p|^2}, compute cell id, count per cell
//    (g_cellcnt zeroed by a captured cudaMemsetAsync before this launch)
// ---------------------------------------------------------------------------
__global__ void build_pts(const float* __restrict__ pos,
                          const float* __restrict__ pnm) {
    int i = blockIdx.x * blockDim.x + threadIdx.x;
    if (i >= Kn) return;
    float x, y, z;
    if (i < Np) { x = pos[i];     y = pos[Np + i];  z = pos[2 * Np + i]; }
    else        { int j = i - Np; x = pnm[j];       y = pnm[Mp + j];  z = pnm[2 * Mp + j]; }
    float sq = x * x + y * y + z * z;
    g_pts[i] = make_float4(x, y, z, sq);
    int cx = min(CELLS - 1, max(0, (int)(x * CSINV)));
    int cy = min(CELLS - 1, max(0, (int)(y * CSINV)));
    int cz = min(CELLS - 1, max(0, (int)(z * CSINV)));
    int cell = (cz * CELLS + cy) * CELLS + cx;
    g_cellid[i] = cell;
    atomicAdd(&g_cellcnt[cell], 1);
}

// ---------------------------------------------------------------------------
// 2. fused exclusive scan (shfl-based, 2 barriers) + scatter.
//    One block, 1024 threads; fill cursors live in shared memory.
// ---------------------------------------------------------------------------
__global__ void scan_scatter() {
    __shared__ int sfill[NCELL];   // 32 KB fill cursors
    __shared__ int wsum[32];
    int t = threadIdx.x;
    int lane = t & 31, warp = t >> 5;

    int loc[8], s = 0;
#pragma unroll
    for (int q = 0; q < 8; q++) {
        int idx = t * 8 + q;
        loc[q] = s;
        if (idx < NCELL) s += g_cellcnt[idx];
    }
    // inclusive warp scan of per-thread sums
    int incl = s;
#pragma unroll
    for (int off = 1; off < 32; off <<= 1) {
        int v = __shfl_up_sync(0xffffffffu, incl, off);
        if (lane >= off) incl += v;
    }
    if (lane == 31) wsum[warp] = incl;
    __syncthreads();
    if (warp == 0) {
        int v = wsum[lane];
        int w = v;
#pragma unroll
        for (int off = 1; off < 32; off <<= 1) {
            int u = __shfl_up_sync(0xffffffffu, w, off);
            if (lane >= off) w += u;
        }
        wsum[lane] = w;
    }
    __syncthreads();
    int base = ((warp > 0) ? wsum[warp - 1] : 0) + incl - s;  // exclusive thread base
#pragma unroll
    for (int q = 0; q < 8; q++) {
        int idx = t * 8 + q;
        if (idx < NCELL) {
            int st = base + loc[q];
            g_cellstart[idx] = st;
            sfill[idx] = st;
        }
    }
    if (t == 1023) g_cellstart[NCELL] = wsum[31];
    __syncthreads();

    // scatter (~6 points per thread); order randomized but nbr rank-sort fixes it
    for (int i = t; i < Kn; i += 1024) {
        int c = g_cellid[i];
        int p = atomicAdd(&sfill[c], 1);
        g_cellpts[p] = i;
    }
}

// ---------------------------------------------------------------------------
// 3. warp-per-node radius search. Lanes scan candidates in parallel;
//    3 x-adjacent cells are contiguous in g_cellpts -> 9 spans per node.
//    Ballot-compacted hits, then rank-sorted ascending (indices unique)
//    -> identical edge list + order as the serial version.
// ---------------------------------------------------------------------------
__global__ void nbr_search() {
    __shared__ int buf[4][MAXNB];
    int wslot = threadIdx.x >> 5;
    int lane  = threadIdx.x & 31;
    int i     = (blockIdx.x * blockDim.x + threadIdx.x) >> 5;
    if (i >= Kn) return;
    float4 pi = g_pts[i];
    int cx = min(CELLS - 1, max(0, (int)(pi.x * CSINV)));
    int cy = min(CELLS - 1, max(0, (int)(pi.y * CSINV)));
    int cz = min(CELLS - 1, max(0, (int)(pi.z * CSINV)));
    int x0 = max(cx - 1, 0), x1 = min(cx + 1, CELLS - 1);
    int* nb = buf[wslot];
    int cnt = 0;
    for (int dz = -1; dz <= 1; dz++) {
        int z = cz + dz;
        if ((unsigned)z >= CELLS) continue;
        for (int dy = -1; dy <= 1; dy++) {
            int y = cy + dy;
            if ((unsigned)y >= CELLS) continue;
            int rowbase = (z * CELLS + y) * CELLS;
            int s = g_cellstart[rowbase + x0];
            int e = g_cellstart[rowbase + x1 + 1];
            for (int t0 = s; t0 < e; t0 += 32) {
                int t = t0 + lane;
                bool ok = false;
                int j = -1;
                if (t < e) {
                    j = g_cellpts[t];
                    float4 pj = g_pts[j];
                    float dot = pi.x * pj.x + pi.y * pj.y + pi.z * pj.z;
                    float d2  = (pi.w + pj.w) - 2.0f * dot;   // identical to reference
                    ok = (d2 < R2);
                }
                unsigned m = __ballot_sync(0xffffffffu, ok);
                if (ok) {
                    int p = cnt + __popc(m & ((1u << lane) - 1u));
                    if (p < MAXNB) nb[p] = j;
                }
                cnt += __popc(m);
                if (cnt > MAXNB) cnt = MAXNB;
            }
        }
    }
    __syncwarp();
    // rank sort: indices unique -> rank = #{u < v} is a permutation
    int v = (lane < cnt) ? nb[lane] : 0x7fffffff;
    int rank = 0;
#pragma unroll
    for (int k = 0; k < 32; k++) {
        int u = __shfl_sync(0xffffffffu, v, k);
        rank += (u < v);
    }
    if (lane < cnt) g_nbr[i * MAXNB + rank] = v;
    if (lane == 0)  g_cnt[i] = cnt;
}

// ---------------------------------------------------------------------------
// 4. h1 = pts @ W1 with fused attention scores (layer 1)
// ---------------------------------------------------------------------------
__global__ void feat1(const float* __restrict__ W1,
                      const float* __restrict__ asrc,
                      const float* __restrict__ adst) {
    __shared__ float S[8], D[8];
    int i = blockIdx.x;
    int c = threadIdx.x;
    float4 p = g_pts[i];
    float v = p.x * W1[c] + p.y * W1[F + c] + p.z * W1[2 * F + c];
    g_h[i * F + c] = v;
    float s = v * asrc[c];   // asrc flattened [H*HID] == channel index
    float d = v * adst[c];
#pragma unroll
    for (int off = 16; off; off >>= 1) {
        s += __shfl_xor_sync(0xffffffffu, s, off);
        d += __shfl_xor_sync(0xffffffffu, d, off);
    }
    int w = c >> 5;
    if ((c & 31) == 0) { S[w] = s; D[w] = d; }
    __syncthreads();
    if (c < H) {
        g_es[i * H + c] = S[2 * c] + S[2 * c + 1];
        g_ed[i * H + c] = D[2 * c] + D[2 * c + 1];
    }
}

// ---------------------------------------------------------------------------
// 5. sparse GAT softmax + aggregation; warp per node.
//    FINAL: only rows [Np, Kn) are ever used -> fuse fc and skip the rest.
// ---------------------------------------------------------------------------
template<bool FINAL>
__global__ void aggregate(const float* __restrict__ bias,
                          const float* __restrict__ fw,
                          const float* __restrict__ fb,
                          float* __restrict__ out) {
    int wi   = (blockIdx.x * blockDim.x + threadIdx.x) >> 5;
    int lane = threadIdx.x & 31;
    if (wi >= (FINAL ? Mp : Kn)) return;
    int node = FINAL ? (Np + wi) : wi;
    int cnt  = g_cnt[node];

    float e[H];
    int nb = 0;
    if (lane < cnt) {
        nb = g_nbr[node * MAXNB + lane];
#pragma unroll
        for (int h = 0; h < H; h++) {
            float v = g_ed[node * H + h] + g_es[nb * H + h];
            e[h] = (v >= 0.f) ? v : SLOPE * v;
        }
    } else {
#pragma unroll
        for (int h = 0; h < H; h++) e[h] = -1e30f;
    }

    float alpha[H];
#pragma unroll
    for (int h = 0; h < H; h++) {
        float m = e[h];
#pragma unroll
        for (int off = 16; off; off >>= 1)
            m = fmaxf(m, __shfl_xor_sync(0xffffffffu, m, off));
        float a = (lane < cnt) ? expf(e[h] - m) : 0.f;
        float s = a;
#pragma unroll
        for (int off = 16; off; off >>= 1)
            s += __shfl_xor_sync(0xffffffffu, s, off);
        alpha[h] = a / s;
    }

    float acc[8] = {0.f, 0.f, 0.f, 0.f, 0.f, 0.f, 0.f, 0.f};
    for (int j = 0; j < cnt; j++) {
        int   nj = __shfl_sync(0xffffffffu, nb, j);
        float aw[H];
#pragma unroll
        for (int h = 0; h < H; h++) aw[h] = __shfl_sync(0xffffffffu, alpha[h], j);
        const float* hr = g_h + nj * F;
#pragma unroll
        for (int r = 0; r < 8; r++)
            acc[r] += aw[r >> 1] * hr[lane + 32 * r];
    }

    float f0 = 0.f, f1 = 0.f;
#pragma unroll
    for (int r = 0; r < 8; r++) {
        int c = lane + 32 * r;
        float v = acc[r] + bias[c];
        v = (v > 0.f) ? v : 0.f;
        if (!FINAL) {
            g_x[node * F + c] = v;
        } else {
            f0 += v * fw[c * 2];
            f1 += v * fw[c * 2 + 1];
        }
    }
    if (FINAL) {
#pragma unroll
        for (int off = 16; off; off >>= 1) {
            f0 += __shfl_xor_sync(0xffffffffu, f0, off);
            f1 += __shfl_xor_sync(0xffffffffu, f1, off);
        }
        if (lane == 0) {
            out[wi * 2]     = f0 + fb[0];
            out[wi * 2 + 1] = f1 + fb[1];
        }
    }
}

// ---------------------------------------------------------------------------
// 6. h2 = x1 @ W2 — BM=64 x BN=64, 128 threads, 8m x 4n per thread.
//    f32x2 over m-pairs: a-pairs come free from aligned LDS.128 quads;
//    b duplicated via register MOVs (16-byte smem strides, benign conflicts).
//    376 blocks -> good SM load balance. One head per block column (BN=64).
// ---------------------------------------------------------------------------
#define BM 64
#define BN 64
#define BKK 16
__global__ void __launch_bounds__(128) gemm2(const float* __restrict__ W,
                                             const float* __restrict__ asrc,
                                             const float* __restrict__ adst) {
    __shared__ __align__(16) float As[BKK][BM];   // transposed: As[k][m]
    __shared__ __align__(16) float Bs[BKK][BN];
    int tid = threadIdx.x;
    int row0 = blockIdx.y * BM, col0 = blockIdx.x * BN;
    int tx = tid & 15, ty = tid >> 4;             // tx: n-quad, ty: m-group of 8 (0..7)
    unsigned long long acc[4][4];                 // acc[mpair][n]
#pragma unroll
    for (int mp = 0; mp < 4; mp++)
#pragma unroll
        for (int n = 0; n < 4; n++) acc[mp][n] = 0ull;

    for (int kk = 0; kk < F; kk += BKK) {
        // A tile: 64 rows x 16 k = 256 float4 loads; 128 threads x 2.
        // Warp = 32 consecutive m, same q -> STS banks = m%32, conflict-free.
#pragma unroll
        for (int it = 0; it < 2; it++) {
            int idx = tid + it * 128;
            int m = idx & 63, q = idx >> 6;       // q in 0..3
            int gr = row0 + m;
            float4 v = make_float4(0.f, 0.f, 0.f, 0.f);
            if (gr < Kn) v = *(const float4*)&g_x[gr * F + kk + q * 4];
            As[q * 4 + 0][m] = v.x; As[q * 4 + 1][m] = v.y;
            As[q * 4 + 2][m] = v.z; As[q * 4 + 3][m] = v.w;
        }
        // B tile: 16 k x 64 n = 256 float4; 128 threads x 2.
#pragma unroll
        for (int it = 0; it < 2; it++) {
            int idx = tid + it * 128;
            int k = idx >> 4, n4 = idx & 15;
            *(float4*)&Bs[k][n4 * 4] = *(const float4*)&W[(kk + k) * F + col0 + n4 * 4];
        }
        __syncthreads();
#pragma unroll
        for (int k = 0; k < BKK; k++) {
            float4 b = *(const float4*)&Bs[k][tx * 4];
            unsigned long long bd[4];
            bd[0] = pack2(b.x, b.x); bd[1] = pack2(b.y, b.y);
            bd[2] = pack2(b.z, b.z); bd[3] = pack2(b.w, b.w);
            float4 a0 = *(const float4*)&As[k][ty * 8];       // m-pairs (0,1),(2,3)
            float4 a1 = *(const float4*)&As[k][ty * 8 + 4];   // m-pairs (4,5),(6,7)
            unsigned long long ap[4];
            ap[0] = pack2(a0.x, a0.y); ap[1] = pack2(a0.z, a0.w);
            ap[2] = pack2(a1.x, a1.y); ap[3] = pack2(a1.z, a1.w);
#pragma unroll
            for (int mp = 0; mp < 4; mp++)
#pragma unroll
                for (int n = 0; n < 4; n++) ffma2(acc[mp][n], ap[mp], bd[n]);
        }
        __syncthreads();
    }

    // epilogue: unpack, store h2, fused es/ed for this head
    float as_[4], ad_[4];
#pragma unroll
    for (int n = 0; n < 4; n++) {
        as_[n] = asrc[col0 + tx * 4 + n];
        ad_[n] = adst[col0 + tx * 4 + n];
    }
    int hidx = col0 >> 6;
#pragma unroll
    for (int mp = 0; mp < 4; mp++) {
        float c0[4], c1[4];                       // rows 2mp, 2mp+1 (within ty group)
#pragma unroll
        for (int n = 0; n < 4; n++) unpack2(acc[mp][n], c0[n], c1[n]);
#pragma unroll
        for (int half = 0; half < 2; half++) {
            float* c = half ? c1 : c0;
            int gr = row0 + ty * 8 + mp * 2 + half;
            float s = c[0] * as_[0] + c[1] * as_[1] + c[2] * as_[2] + c[3] * as_[3];
            float d = c[0] * ad_[0] + c[1] * ad_[1] + c[2] * ad_[2] + c[3] * ad_[3];
#pragma unroll
            for (int off = 8; off; off >>= 1) {   // reduce across the 16 tx lanes
                s += __shfl_xor_sync(0xffffffffu, s, off);
                d += __shfl_xor_sync(0xffffffffu, d, off);
            }
            if (gr < Kn) {
                *(float4*)&g_h[gr * F + col0 + tx * 4] =
                    make_float4(c[0], c[1], c[2], c[3]);
                if (tx == 0) {
                    g_es[gr * H + hidx] = s;
                    g_ed[gr * H + hidx] = d;
                }
            }
        }
    }
}

// ---------------------------------------------------------------------------
extern "C" void kernel_launch(void* const* d_in, const int* in_sizes, int n_in,
                              void* d_out, int out_size) {
    const float* pos   = (const float*)d_in[0];
    const float* pnm   = (const float*)d_in[1];
    const float* W1    = (const float*)d_in[2];
    const float* asrc1 = (const float*)d_in[3];
    const float* adst1 = (const float*)d_in[4];
    const float* b1    = (const float*)d_in[5];
    const float* W2    = (const float*)d_in[6];
    const float* asrc2 = (const float*)d_in[7];
    const float* adst2 = (const float*)d_in[8];
    const float* b2    = (const float*)d_in[9];
    const float* fw    = (const float*)d_in[10];
    const float* fb    = (const float*)d_in[11];
    float* out = (float*)d_out;

    // zero the cell histogram via a captured memset node (replaces a kernel)
    void* cellcnt_ptr = nullptr;
    cudaGetSymbolAddress(&cellcnt_ptr, g_cellcnt);
    cudaMemsetAsync(cellcnt_ptr, 0, NCELL * sizeof(int));

    build_pts<<<(Kn + 255) / 256, 256>>>(pos, pnm);
    scan_scatter<<<1, 1024>>>();
    nbr_search<<<(Kn * 32 + 127) / 128, 128>>>();

    // ---- GAT layer 1 (scores fused into feat1) ----
    feat1<<<Kn, F>>>(W1, asrc1, adst1);
    aggregate<false><<<(Kn * 32 + 255) / 256, 256>>>(b1, nullptr, nullptr, nullptr);

    // ---- GAT layer 2 (scores fused into gemm2 epilogue) ----
    gemm2<<<dim3(F / BN, (Kn + BM - 1) / BM), 128>>>(W2, asrc2, adst2);
    aggregate<true><<<(Mp * 32 + 255) / 256, 256>>>(b2, fw, fb, out);
}

// round 12
// speedup vs baseline: 1.2036x; 1.0034x over previous
#include <cuda_runtime.h>

#define Kn 6000
#define Np 3000
#define Mp 3000
#define F 256
#define H 4
#define HID 64
#define MAXNB 32
#define R2 0.0025f
#define SLOPE 0.2f

#define CELLS 20
#define NCELL (CELLS * CELLS * CELLS)
#define CSINV 19.8019801980198f   /* 1 / 0.0505 ; cell > max accepted pair dist */

#define FNODES 8                  /* nodes per feat1 block */

// ---- device scratch (no dynamic allocation allowed) ----
__device__ float4 g_pts[Kn];
__device__ int    g_cellid[Kn];
__device__ int    g_cellcnt[NCELL];
__device__ int    g_cellstart[NCELL + 1];
__device__ int    g_cellpts[Kn];
__device__ int    g_nbr[Kn * MAXNB];
__device__ int    g_cnt[Kn];
__device__ float  g_h[Kn * F];
__device__ float  g_x[Kn * F];
__device__ float  g_es[Kn * H];
__device__ float  g_ed[Kn * H];

// ---- packed f32x2 helpers (bit-identical rn fp32 per lane, 2x FMA pipe) ----
__device__ __forceinline__ unsigned long long pack2(float lo, float hi) {
    unsigned long long r;
    asm("mov.b64 %0, {%1, %2};" : "=l"(r) : "f"(lo), "f"(hi));
    return r;
}
__device__ __forceinline__ void unpack2(unsigned long long v, float& lo, float& hi) {
    asm("mov.b64 {%0, %1}, %2;" : "=f"(lo), "=f"(hi) : "l"(v));
}
__device__ __forceinline__ void ffma2(unsigned long long& acc,
                                      unsigned long long a, unsigned long long b) {
    asm("fma.rn.f32x2 %0, %1, %2, %0;" : "+l"(acc) : "l"(a), "l"(b));
}

// ---------------------------------------------------------------------------
// 1. pack points {x,y,z,|p|^2}, compute cell id, count per cell
//    (g_cellcnt zeroed by a captured cudaMemsetAsync before this launch)
// ---------------------------------------------------------------------------
__global__ void build_pts(const float* __restrict__ pos,
                          const float* __restrict__ pnm) {
    int i = blockIdx.x * blockDim.x + threadIdx.x;
    if (i >= Kn) return;
    float x, y, z;
    if (i < Np) { x = pos[i];     y = pos[Np + i];  z = pos[2 * Np + i]; }
    else        { int j = i - Np; x = pnm[j];       y = pnm[Mp + j];  z = pnm[2 * Mp + j]; }
    float sq = x * x + y * y + z * z;
    g_pts[i] = make_float4(x, y, z, sq);
    int cx = min(CELLS - 1, max(0, (int)(x * CSINV)));
    int cy = min(CELLS - 1, max(0, (int)(y * CSINV)));
    int cz = min(CELLS - 1, max(0, (int)(z * CSINV)));
    int cell = (cz * CELLS + cy) * CELLS + cx;
    g_cellid[i] = cell;
    atomicAdd(&g_cellcnt[cell], 1);
}

// ---------------------------------------------------------------------------
// 2. fused exclusive scan (shfl-based, 2 barriers) + scatter.
//    One block, 1024 threads; fill cursors live in shared memory.
// ---------------------------------------------------------------------------
__global__ void scan_scatter() {
    __shared__ int sfill[NCELL];   // 32 KB fill cursors
    __shared__ int wsum[32];
    int t = threadIdx.x;
    int lane = t & 31, warp = t >> 5;

    int loc[8], s = 0;
#pragma unroll
    for (int q = 0; q < 8; q++) {
        int idx = t * 8 + q;
        loc[q] = s;
        if (idx < NCELL) s += g_cellcnt[idx];
    }
    // inclusive warp scan of per-thread sums
    int incl = s;
#pragma unroll
    for (int off = 1; off < 32; off <<= 1) {
        int v = __shfl_up_sync(0xffffffffu, incl, off);
        if (lane >= off) incl += v;
    }
    if (lane == 31) wsum[warp] = incl;
    __syncthreads();
    if (warp == 0) {
        int v = wsum[lane];
        int w = v;
#pragma unroll
        for (int off = 1; off < 32; off <<= 1) {
            int u = __shfl_up_sync(0xffffffffu, w, off);
            if (lane >= off) w += u;
        }
        wsum[lane] = w;
    }
    __syncthreads();
    int base = ((warp > 0) ? wsum[warp - 1] : 0) + incl - s;  // exclusive thread base
#pragma unroll
    for (int q = 0; q < 8; q++) {
        int idx = t * 8 + q;
        if (idx < NCELL) {
            int st = base + loc[q];
            g_cellstart[idx] = st;
            sfill[idx] = st;
        }
    }
    if (t == 1023) g_cellstart[NCELL] = wsum[31];
    __syncthreads();

    // scatter (~6 points per thread); order randomized but nbr rank-sort fixes it
    for (int i = t; i < Kn; i += 1024) {
        int c = g_cellid[i];
        int p = atomicAdd(&sfill[c], 1);
        g_cellpts[p] = i;
    }
}

// ---------------------------------------------------------------------------
// 3. warp-per-node radius search. Lanes scan candidates in parallel;
//    3 x-adjacent cells are contiguous in g_cellpts -> 9 spans per node.
//    Ballot-compacted hits, then rank-sorted ascending (indices unique)
//    -> identical edge list + order as the serial version.
// ---------------------------------------------------------------------------
__global__ void nbr_search() {
    __shared__ int buf[4][MAXNB];
    int wslot = threadIdx.x >> 5;
    int lane  = threadIdx.x & 31;
    int i     = (blockIdx.x * blockDim.x + threadIdx.x) >> 5;
    if (i >= Kn) return;
    float4 pi = g_pts[i];
    int cx = min(CELLS - 1, max(0, (int)(pi.x * CSINV)));
    int cy = min(CELLS - 1, max(0, (int)(pi.y * CSINV)));
    int cz = min(CELLS - 1, max(0, (int)(pi.z * CSINV)));
    int x0 = max(cx - 1, 0), x1 = min(cx + 1, CELLS - 1);
    int* nb = buf[wslot];
    int cnt = 0;
    for (int dz = -1; dz <= 1; dz++) {
        int z = cz + dz;
        if ((unsigned)z >= CELLS) continue;
        for (int dy = -1; dy <= 1; dy++) {
            int y = cy + dy;
            if ((unsigned)y >= CELLS) continue;
            int rowbase = (z * CELLS + y) * CELLS;
            int s = g_cellstart[rowbase + x0];
            int e = g_cellstart[rowbase + x1 + 1];
            for (int t0 = s; t0 < e; t0 += 32) {
                int t = t0 + lane;
                bool ok = false;
                int j = -1;
                if (t < e) {
                    j = g_cellpts[t];
                    float4 pj = g_pts[j];
                    float dot = pi.x * pj.x + pi.y * pj.y + pi.z * pj.z;
                    float d2  = (pi.w + pj.w) - 2.0f * dot;   // identical to reference
                    ok = (d2 < R2);
                }
                unsigned m = __ballot_sync(0xffffffffu, ok);
                if (ok) {
                    int p = cnt + __popc(m & ((1u << lane) - 1u));
                    if (p < MAXNB) nb[p] = j;
                }
                cnt += __popc(m);
                if (cnt > MAXNB) cnt = MAXNB;
            }
        }
    }
    __syncwarp();
    // rank sort: indices unique -> rank = #{u < v} is a permutation
    int v = (lane < cnt) ? nb[lane] : 0x7fffffff;
    int rank = 0;
#pragma unroll
    for (int k = 0; k < 32; k++) {
        int u = __shfl_sync(0xffffffffu, v, k);
        rank += (u < v);
    }
    if (lane < cnt) g_nbr[i * MAXNB + rank] = v;
    if (lane == 0)  g_cnt[i] = cnt;
}

// ---------------------------------------------------------------------------
// 4. h1 = pts @ W1 with fused attention scores (layer 1).
//    FNODES nodes per block: W1 column + attention weights live in registers
//    across the node loop; identical op order per node as the 1-node version.
// ---------------------------------------------------------------------------
__global__ void feat1(const float* __restrict__ W1,
                      const float* __restrict__ asrc,
                      const float* __restrict__ adst) {
    __shared__ float S[FNODES][8], D[FNODES][8];
    int c = threadIdx.x;
    int lane = c & 31, warp = c >> 5;
    float w0 = W1[c], w1 = W1[F + c], w2 = W1[2 * F + c];
    float as = asrc[c], ad = adst[c];
    int i0 = blockIdx.x * FNODES;
#pragma unroll
    for (int n = 0; n < FNODES; n++) {
        int i = i0 + n;
        float4 p = g_pts[i];                      // broadcast load
        float v = p.x * w0 + p.y * w1 + p.z * w2;
        g_h[i * F + c] = v;
        float s = v * as;
        float d = v * ad;
#pragma unroll
        for (int off = 16; off; off >>= 1) {
            s += __shfl_xor_sync(0xffffffffu, s, off);
            d += __shfl_xor_sync(0xffffffffu, d, off);
        }
        if (lane == 0) { S[n][warp] = s; D[n][warp] = d; }
    }
    __syncthreads();
    if (c < FNODES * H) {                         // 32 threads: n = c>>2, h = c&3
        int n = c >> 2, h = c & 3;
        g_es[(i0 + n) * H + h] = S[n][2 * h] + S[n][2 * h + 1];
        g_ed[(i0 + n) * H + h] = D[n][2 * h] + D[n][2 * h + 1];
    }
}

// ---------------------------------------------------------------------------
// 5. sparse GAT softmax + aggregation; warp per node.
//    FINAL: only rows [Np, Kn) are ever used -> fuse fc and skip the rest.
// ---------------------------------------------------------------------------
template<bool FINAL>
__global__ void aggregate(const float* __restrict__ bias,
                          const float* __restrict__ fw,
                          const float* __restrict__ fb,
                          float* __restrict__ out) {
    int wi   = (blockIdx.x * blockDim.x + threadIdx.x) >> 5;
    int lane = threadIdx.x & 31;
    if (wi >= (FINAL ? Mp : Kn)) return;
    int node = FINAL ? (Np + wi) : wi;
    int cnt  = g_cnt[node];

    float e[H];
    int nb = 0;
    if (lane < cnt) {
        nb = g_nbr[node * MAXNB + lane];
#pragma unroll
        for (int h = 0; h < H; h++) {
            float v = g_ed[node * H + h] + g_es[nb * H + h];
            e[h] = (v >= 0.f) ? v : SLOPE * v;
        }
    } else {
#pragma unroll
        for (int h = 0; h < H; h++) e[h] = -1e30f;
    }

    float alpha[H];
#pragma unroll
    for (int h = 0; h < H; h++) {
        float m = e[h];
#pragma unroll
        for (int off = 16; off; off >>= 1)
            m = fmaxf(m, __shfl_xor_sync(0xffffffffu, m, off));
        float a = (lane < cnt) ? expf(e[h] - m) : 0.f;
        float s = a;
#pragma unroll
        for (int off = 16; off; off >>= 1)
            s += __shfl_xor_sync(0xffffffffu, s, off);
        alpha[h] = a / s;
    }

    float acc[8] = {0.f, 0.f, 0.f, 0.f, 0.f, 0.f, 0.f, 0.f};
    for (int j = 0; j < cnt; j++) {
        int   nj = __shfl_sync(0xffffffffu, nb, j);
        float aw[H];
#pragma unroll
        for (int h = 0; h < H; h++) aw[h] = __shfl_sync(0xffffffffu, alpha[h], j);
        const float* hr = g_h + nj * F;
#pragma unroll
        for (int r = 0; r < 8; r++)
            acc[r] += aw[r >> 1] * hr[lane + 32 * r];
    }

    float f0 = 0.f, f1 = 0.f;
#pragma unroll
    for (int r = 0; r < 8; r++) {
        int c = lane + 32 * r;
        float v = acc[r] + bias[c];
        v = (v > 0.f) ? v : 0.f;
        if (!FINAL) {
            g_x[node * F + c] = v;
        } else {
            f0 += v * fw[c * 2];
            f1 += v * fw[c * 2 + 1];
        }
    }
    if (FINAL) {
#pragma unroll
        for (int off = 16; off; off >>= 1) {
            f0 += __shfl_xor_sync(0xffffffffu, f0, off);
            f1 += __shfl_xor_sync(0xffffffffu, f1, off);
        }
        if (lane == 0) {
            out[wi * 2]     = f0 + fb[0];
            out[wi * 2 + 1] = f1 + fb[1];
        }
    }
}

// ---------------------------------------------------------------------------
// 6. h2 = x1 @ W2 — BM=64 x BN=64, 128 threads, 8m x 4n per thread.
//    f32x2 over m-pairs: a-pairs come free from aligned LDS.128 quads;
//    b duplicated via register MOVs (16-byte smem strides, benign conflicts).
//    376 blocks -> good SM load balance. One head per block column (BN=64).
// ---------------------------------------------------------------------------
#define BM 64
#define BN 64
#define BKK 16
__global__ void __launch_bounds__(128) gemm2(const float* __restrict__ W,
                                             const float* __restrict__ asrc,
                                             const float* __restrict__ adst) {
    __shared__ __align__(16) float As[BKK][BM];   // transposed: As[k][m]
    __shared__ __align__(16) float Bs[BKK][BN];
    int tid = threadIdx.x;
    int row0 = blockIdx.y * BM, col0 = blockIdx.x * BN;
    int tx = tid & 15, ty = tid >> 4;             // tx: n-quad, ty: m-group of 8 (0..7)
    unsigned long long acc[4][4];                 // acc[mpair][n]
#pragma unroll
    for (int mp = 0; mp < 4; mp++)
#pragma unroll
        for (int n = 0; n < 4; n++) acc[mp][n] = 0ull;

    for (int kk = 0; kk < F; kk += BKK) {
        // A tile: 64 rows x 16 k = 256 float4 loads; 128 threads x 2.
        // Warp = 32 consecutive m, same q -> STS banks = m%32, conflict-free.
#pragma unroll
        for (int it = 0; it < 2; it++) {
            int idx = tid + it * 128;
            int m = idx & 63, q = idx >> 6;       // q in 0..3
            int gr = row0 + m;
            float4 v = make_float4(0.f, 0.f, 0.f, 0.f);
            if (gr < Kn) v = *(const float4*)&g_x[gr * F + kk + q * 4];
            As[q * 4 + 0][m] = v.x; As[q * 4 + 1][m] = v.y;
            As[q * 4 + 2][m] = v.z; As[q * 4 + 3][m] = v.w;
        }
        // B tile: 16 k x 64 n = 256 float4; 128 threads x 2.
#pragma unroll
        for (int it = 0; it < 2; it++) {
            int idx = tid + it * 128;
            int k = idx >> 4, n4 = idx & 15;
            *(float4*)&Bs[k][n4 * 4] = *(const float4*)&W[(kk + k) * F + col0 + n4 * 4];
        }
        __syncthreads();
#pragma unroll
        for (int k = 0; k < BKK; k++) {
            float4 b = *(const float4*)&Bs[k][tx * 4];
            unsigned long long bd[4];
            bd[0] = pack2(b.x, b.x); bd[1] = pack2(b.y, b.y);
            bd[2] = pack2(b.z, b.z); bd[3] = pack2(b.w, b.w);
            float4 a0 = *(const float4*)&As[k][ty * 8];       // m-pairs (0,1),(2,3)
            float4 a1 = *(const float4*)&As[k][ty * 8 + 4];   // m-pairs (4,5),(6,7)
            unsigned long long ap[4];
            ap[0] = pack2(a0.x, a0.y); ap[1] = pack2(a0.z, a0.w);
            ap[2] = pack2(a1.x, a1.y); ap[3] = pack2(a1.z, a1.w);
#pragma unroll
            for (int mp = 0; mp < 4; mp++)
#pragma unroll
                for (int n = 0; n < 4; n++) ffma2(acc[mp][n], ap[mp], bd[n]);
        }
        __syncthreads();
    }

    // epilogue: unpack, store h2, fused es/ed for this head
    float as_[4], ad_[4];
#pragma unroll
    for (int n = 0; n < 4; n++) {
        as_[n] = asrc[col0 + tx * 4 + n];
        ad_[n] = adst[col0 + tx * 4 + n];
    }
    int hidx = col0 >> 6;
#pragma unroll
    for (int mp = 0; mp < 4; mp++) {
        float c0[4], c1[4];                       // rows 2mp, 2mp+1 (within ty group)
#pragma unroll
        for (int n = 0; n < 4; n++) unpack2(acc[mp][n], c0[n], c1[n]);
#pragma unroll
        for (int half = 0; half < 2; half++) {
            float* c = half ? c1 : c0;
            int gr = row0 + ty * 8 + mp * 2 + half;
            float s = c[0] * as_[0] + c[1] * as_[1] + c[2] * as_[2] + c[3] * as_[3];
            float d = c[0] * ad_[0] + c[1] * ad_[1] + c[2] * ad_[2] + c[3] * ad_[3];
#pragma unroll
            for (int off = 8; off; off >>= 1) {   // reduce across the 16 tx lanes
                s += __shfl_xor_sync(0xffffffffu, s, off);
                d += __shfl_xor_sync(0xffffffffu, d, off);
            }
            if (gr < Kn) {
                *(float4*)&g_h[gr * F + col0 + tx * 4] =
                    make_float4(c[0], c[1], c[2], c[3]);
                if (tx == 0) {
                    g_es[gr * H + hidx] = s;
                    g_ed[gr * H + hidx] = d;
                }
            }
        }
    }
}

// ---------------------------------------------------------------------------
extern "C" void kernel_launch(void* const* d_in, const int* in_sizes, int n_in,
                              void* d_out, int out_size) {
    const float* pos   = (const float*)d_in[0];
    const float* pnm   = (const float*)d_in[1];
    const float* W1    = (const float*)d_in[2];
    const float* asrc1 = (const float*)d_in[3];
    const float* adst1 = (const float*)d_in[4];
    const float* b1    = (const float*)d_in[5];
    const float* W2    = (const float*)d_in[6];
    const float* asrc2 = (const float*)d_in[7];
    const float* adst2 = (const float*)d_in[8];
    const float* b2    = (const float*)d_in[9];
    const float* fw    = (const float*)d_in[10];
    const float* fb    = (const float*)d_in[11];
    float* out = (float*)d_out;

    // zero the cell histogram via a captured memset node (replaces a kernel)
    void* cellcnt_ptr = nullptr;
    cudaGetSymbolAddress(&cellcnt_ptr, g_cellcnt);
    cudaMemsetAsync(cellcnt_ptr, 0, NCELL * sizeof(int));

    build_pts<<<(Kn + 255) / 256, 256>>>(pos, pnm);
    scan_scatter<<<1, 1024>>>();
    nbr_search<<<(Kn * 32 + 127) / 128, 128>>>();

    // ---- GAT layer 1 (scores fused into feat1) ----
    feat1<<<Kn / FNODES, F>>>(W1, asrc1, adst1);
    aggregate<false><<<(Kn * 32 + 255) / 256, 256>>>(b1, nullptr, nullptr, nullptr);

    // ---- GAT layer 2 (scores fused into gemm2 epilogue) ----
    gemm2<<<dim3(F / BN, (Kn + BM - 1) / BM), 128>>>(W2, asrc2, adst2);
    aggregate<true><<<(Mp * 32 + 255) / 256, 256>>>(b2, fw, fb, out);
}

// round 13
// speedup vs baseline: 1.2170x; 1.0112x over previous
#include <cuda_runtime.h>

#define Kn 6000
#define Np 3000
#define Mp 3000
#define F 256
#define H 4
#define HID 64
#define MAXNB 32
#define R2 0.0025f
#define SLOPE 0.2f

#define CELLS 20
#define NCELL (CELLS * CELLS * CELLS)
#define CSINV 19.8019801980198f   /* 1 / 0.0505 ; cell > max accepted pair dist */

#define FNODES 8                  /* nodes per feat1 block */

// ---- device scratch (no dynamic allocation allowed) ----
__device__ float4 g_pts[Kn];
__device__ int    g_cellid[Kn];
__device__ int    g_cellcnt[NCELL];
__device__ int    g_cellstart[NCELL + 1];
__device__ int    g_cellpts[Kn];
__device__ int    g_nbr[Kn * MAXNB];
__device__ int    g_cnt[Kn];
__device__ float  g_h[Kn * F];
__device__ float  g_x[Kn * F];
__device__ float  g_es[Kn * H];
__device__ float  g_ed[Kn * H];

// ---- packed f32x2 helpers (bit-identical rn fp32 per lane, 2x FMA pipe) ----
__device__ __forceinline__ unsigned long long pack2(float lo, float hi) {
    unsigned long long r;
    asm("mov.b64 %0, {%1, %2};" : "=l"(r) : "f"(lo), "f"(hi));
    return r;
}
__device__ __forceinline__ void unpack2(unsigned long long v, float& lo, float& hi) {
    asm("mov.b64 {%0, %1}, %2;" : "=f"(lo), "=f"(hi) : "l"(v));
}
__device__ __forceinline__ void ffma2(unsigned long long& acc,
                                      unsigned long long a, unsigned long long b) {
    asm("fma.rn.f32x2 %0, %1, %2, %0;" : "+l"(acc) : "l"(a), "l"(b));
}
__device__ __forceinline__ void fadd2(unsigned long long& acc, unsigned long long o) {
    asm("add.rn.f32x2 %0, %0, %1;" : "+l"(acc) : "l"(o));
}

// ---------------------------------------------------------------------------
// 1. pack points {x,y,z,|p|^2}, compute cell id, count per cell
//    (g_cellcnt zeroed by a captured cudaMemsetAsync before this launch)
// ---------------------------------------------------------------------------
__global__ void build_pts(const float* __restrict__ pos,
                          const float* __restrict__ pnm) {
    int i = blockIdx.x * blockDim.x + threadIdx.x;
    if (i >= Kn) return;
    float x, y, z;
    if (i < Np) { x = pos[i];     y = pos[Np + i];  z = pos[2 * Np + i]; }
    else        { int j = i - Np; x = pnm[j];       y = pnm[Mp + j];  z = pnm[2 * Mp + j]; }
    float sq = x * x + y * y + z * z;
    g_pts[i] = make_float4(x, y, z, sq);
    int cx = min(CELLS - 1, max(0, (int)(x * CSINV)));
    int cy = min(CELLS - 1, max(0, (int)(y * CSINV)));
    int cz = min(CELLS - 1, max(0, (int)(z * CSINV)));
    int cell = (cz * CELLS + cy) * CELLS + cx;
    g_cellid[i] = cell;
    atomicAdd(&g_cellcnt[cell], 1);
}

// ---------------------------------------------------------------------------
// 2. fused exclusive scan (shfl-based, 2 barriers) + scatter.
//    One block, 1024 threads; fill cursors live in shared memory.
// ---------------------------------------------------------------------------
__global__ void scan_scatter() {
    __shared__ int sfill[NCELL];   // 32 KB fill cursors
    __shared__ int wsum[32];
    int t = threadIdx.x;
    int lane = t & 31, warp = t >> 5;

    int loc[8], s = 0;
#pragma unroll
    for (int q = 0; q < 8; q++) {
        int idx = t * 8 + q;
        loc[q] = s;
        if (idx < NCELL) s += g_cellcnt[idx];
    }
    // inclusive warp scan of per-thread sums
    int incl = s;
#pragma unroll
    for (int off = 1; off < 32; off <<= 1) {
        int v = __shfl_up_sync(0xffffffffu, incl, off);
        if (lane >= off) incl += v;
    }
    if (lane == 31) wsum[warp] = incl;
    __syncthreads();
    if (warp == 0) {
        int v = wsum[lane];
        int w = v;
#pragma unroll
        for (int off = 1; off < 32; off <<= 1) {
            int u = __shfl_up_sync(0xffffffffu, w, off);
            if (lane >= off) w += u;
        }
        wsum[lane] = w;
    }
    __syncthreads();
    int base = ((warp > 0) ? wsum[warp - 1] : 0) + incl - s;  // exclusive thread base
#pragma unroll
    for (int q = 0; q < 8; q++) {
        int idx = t * 8 + q;
        if (idx < NCELL) {
            int st = base + loc[q];
            g_cellstart[idx] = st;
            sfill[idx] = st;
        }
    }
    if (t == 1023) g_cellstart[NCELL] = wsum[31];
    __syncthreads();

    // scatter (~6 points per thread); order randomized but nbr rank-sort fixes it
    for (int i = t; i < Kn; i += 1024) {
        int c = g_cellid[i];
        int p = atomicAdd(&sfill[c], 1);
        g_cellpts[p] = i;
    }
}

// ---------------------------------------------------------------------------
// 3. warp-per-node radius search. Lanes scan candidates in parallel;
//    3 x-adjacent cells are contiguous in g_cellpts -> 9 spans per node.
//    Ballot-compacted hits, then rank-sorted ascending (indices unique)
//    -> identical edge list + order as the serial version.
// ---------------------------------------------------------------------------
__global__ void nbr_search() {
    __shared__ int buf[4][MAXNB];
    int wslot = threadIdx.x >> 5;
    int lane  = threadIdx.x & 31;
    int i     = (blockIdx.x * blockDim.x + threadIdx.x) >> 5;
    if (i >= Kn) return;
    float4 pi = g_pts[i];
    int cx = min(CELLS - 1, max(0, (int)(pi.x * CSINV)));
    int cy = min(CELLS - 1, max(0, (int)(pi.y * CSINV)));
    int cz = min(CELLS - 1, max(0, (int)(pi.z * CSINV)));
    int x0 = max(cx - 1, 0), x1 = min(cx + 1, CELLS - 1);
    int* nb = buf[wslot];
    int cnt = 0;
    for (int dz = -1; dz <= 1; dz++) {
        int z = cz + dz;
        if ((unsigned)z >= CELLS) continue;
        for (int dy = -1; dy <= 1; dy++) {
            int y = cy + dy;
            if ((unsigned)y >= CELLS) continue;
            int rowbase = (z * CELLS + y) * CELLS;
            int s = g_cellstart[rowbase + x0];
            int e = g_cellstart[rowbase + x1 + 1];
            for (int t0 = s; t0 < e; t0 += 32) {
                int t = t0 + lane;
                bool ok = false;
                int j = -1;
                if (t < e) {
                    j = g_cellpts[t];
                    float4 pj = g_pts[j];
                    float dot = pi.x * pj.x + pi.y * pj.y + pi.z * pj.z;
                    float d2  = (pi.w + pj.w) - 2.0f * dot;   // identical to reference
                    ok = (d2 < R2);
                }
                unsigned m = __ballot_sync(0xffffffffu, ok);
                if (ok) {
                    int p = cnt + __popc(m & ((1u << lane) - 1u));
                    if (p < MAXNB) nb[p] = j;
                }
                cnt += __popc(m);
                if (cnt > MAXNB) cnt = MAXNB;
            }
        }
    }
    __syncwarp();
    // rank sort: indices unique -> rank = #{u < v} is a permutation
    int v = (lane < cnt) ? nb[lane] : 0x7fffffff;
    int rank = 0;
#pragma unroll
    for (int k = 0; k < 32; k++) {
        int u = __shfl_sync(0xffffffffu, v, k);
        rank += (u < v);
    }
    if (lane < cnt) g_nbr[i * MAXNB + rank] = v;
    if (lane == 0)  g_cnt[i] = cnt;
}

// ---------------------------------------------------------------------------
// 4. h1 = pts @ W1 with fused attention scores (layer 1).
//    FNODES nodes per block; W1 column + attention weights in registers.
// ---------------------------------------------------------------------------
__global__ void feat1(const float* __restrict__ W1,
                      const float* __restrict__ asrc,
                      const float* __restrict__ adst) {
    __shared__ float S[FNODES][8], D[FNODES][8];
    int c = threadIdx.x;
    int lane = c & 31, warp = c >> 5;
    float w0 = W1[c], w1 = W1[F + c], w2 = W1[2 * F + c];
    float as = asrc[c], ad = adst[c];
    int i0 = blockIdx.x * FNODES;
#pragma unroll
    for (int n = 0; n < FNODES; n++) {
        int i = i0 + n;
        float4 p = g_pts[i];                      // broadcast load
        float v = p.x * w0 + p.y * w1 + p.z * w2;
        g_h[i * F + c] = v;
        float s = v * as;
        float d = v * ad;
#pragma unroll
        for (int off = 16; off; off >>= 1) {
            s += __shfl_xor_sync(0xffffffffu, s, off);
            d += __shfl_xor_sync(0xffffffffu, d, off);
        }
        if (lane == 0) { S[n][warp] = s; D[n][warp] = d; }
    }
    __syncthreads();
    if (c < FNODES * H) {                         // 32 threads: n = c>>2, h = c&3
        int n = c >> 2, h = c & 3;
        g_es[(i0 + n) * H + h] = S[n][2 * h] + S[n][2 * h + 1];
        g_ed[(i0 + n) * H + h] = D[n][2 * h] + D[n][2 * h + 1];
    }
}

// ---------------------------------------------------------------------------
// 5. sparse GAT softmax + aggregation; warp per node.
//    FINAL: only rows [Np, Kn) are ever used -> fuse fc and skip the rest.
// ---------------------------------------------------------------------------
template<bool FINAL>
__global__ void aggregate(const float* __restrict__ bias,
                          const float* __restrict__ fw,
                          const float* __restrict__ fb,
                          float* __restrict__ out) {
    int wi   = (blockIdx.x * blockDim.x + threadIdx.x) >> 5;
    int lane = threadIdx.x & 31;
    if (wi >= (FINAL ? Mp : Kn)) return;
    int node = FINAL ? (Np + wi) : wi;
    int cnt  = g_cnt[node];

    float e[H];
    int nb = 0;
    if (lane < cnt) {
        nb = g_nbr[node * MAXNB + lane];
#pragma unroll
        for (int h = 0; h < H; h++) {
            float v = g_ed[node * H + h] + g_es[nb * H + h];
            e[h] = (v >= 0.f) ? v : SLOPE * v;
        }
    } else {
#pragma unroll
        for (int h = 0; h < H; h++) e[h] = -1e30f;
    }

    float alpha[H];
#pragma unroll
    for (int h = 0; h < H; h++) {
        float m = e[h];
#pragma unroll
        for (int off = 16; off; off >>= 1)
            m = fmaxf(m, __shfl_xor_sync(0xffffffffu, m, off));
        float a = (lane < cnt) ? expf(e[h] - m) : 0.f;
        float s = a;
#pragma unroll
        for (int off = 16; off; off >>= 1)
            s += __shfl_xor_sync(0xffffffffu, s, off);
        alpha[h] = a / s;
    }

    float acc[8] = {0.f, 0.f, 0.f, 0.f, 0.f, 0.f, 0.f, 0.f};
    for (int j = 0; j < cnt; j++) {
        int   nj = __shfl_sync(0xffffffffu, nb, j);
        float aw[H];
#pragma unroll
        for (int h = 0; h < H; h++) aw[h] = __shfl_sync(0xffffffffu, alpha[h], j);
        const float* hr = g_h + nj * F;
#pragma unroll
        for (int r = 0; r < 8; r++)
            acc[r] += aw[r >> 1] * hr[lane + 32 * r];
    }

    float f0 = 0.f, f1 = 0.f;
#pragma unroll
    for (int r = 0; r < 8; r++) {
        int c = lane + 32 * r;
        float v = acc[r] + bias[c];
        v = (v > 0.f) ? v : 0.f;
        if (!FINAL) {
            g_x[node * F + c] = v;
        } else {
            f0 += v * fw[c * 2];
            f1 += v * fw[c * 2 + 1];
        }
    }
    if (FINAL) {
#pragma unroll
        for (int off = 16; off; off >>= 1) {
            f0 += __shfl_xor_sync(0xffffffffu, f0, off);
            f1 += __shfl_xor_sync(0xffffffffu, f1, off);
        }
        if (lane == 0) {
            out[wi * 2]     = f0 + fb[0];
            out[wi * 2 + 1] = f1 + fb[1];
        }
    }
}

// ---------------------------------------------------------------------------
// 6. h2 = x1 @ W2 — BM=64 x BN=64, 256 threads, SPLIT-K=2.
//    Group kg processes k in [kg*128, kg*128+128); partials combined through
//    smem in fixed order (group0 + group1) -> deterministic. 20 warps/SM.
//    m-pair FFMA2 inner loop (a-pairs free from aligned LDS.128 quads).
// ---------------------------------------------------------------------------
#define BM 64
#define BN 64
#define BKT 32
__global__ void __launch_bounds__(256) gemm2(const float* __restrict__ W,
                                             const float* __restrict__ asrc,
                                             const float* __restrict__ adst) {
    __shared__ __align__(16) float smem_buf[BKT * BM + BKT * BN];  // 16 KB
    float* As = smem_buf;                 // As[k][m] = As[k*BM+m], transposed
    float* Bs = smem_buf + BKT * BM;      // Bs[k][n] = Bs[k*BN+n]
    int tid = threadIdx.x;
    int kg = tid >> 7;                    // split-K group: 0 or 1
    int wg_tid = tid & 127;
    int row0 = blockIdx.y * BM, col0 = blockIdx.x * BN;
    int tx = wg_tid & 15, ty = wg_tid >> 4;   // tx: n-quad, ty: m-group of 8
    unsigned long long acc[4][4];             // acc[mpair][n]
#pragma unroll
    for (int mp = 0; mp < 4; mp++)
#pragma unroll
        for (int n = 0; n < 4; n++) acc[mp][n] = 0ull;

    for (int kk = 0; kk < F; kk += BKT) {
        // A tile: 64 rows x 32 k = 512 float4; 256 threads x 2. Transposed STS:
        // warp = 32 consecutive m, same q -> banks m%32, conflict-free.
#pragma unroll
        for (int it = 0; it < 2; it++) {
            int idx = tid + it * 256;
            int m = idx & 63, q = idx >> 6;       // q in 0..7
            int gr = row0 + m;
            float4 v = make_float4(0.f, 0.f, 0.f, 0.f);
            if (gr < Kn) v = *(const float4*)&g_x[gr * F + kk + q * 4];
            As[(q * 4 + 0) * BM + m] = v.x; As[(q * 4 + 1) * BM + m] = v.y;
            As[(q * 4 + 2) * BM + m] = v.z; As[(q * 4 + 3) * BM + m] = v.w;
        }
        // B tile: 32 k x 64 n = 512 float4; consecutive lanes -> conflict-free.
#pragma unroll
        for (int it = 0; it < 2; it++) {
            int idx = tid + it * 256;
            int k = idx >> 4, n4 = idx & 15;
            *(float4*)&Bs[k * BN + n4 * 4] =
                *(const float4*)&W[(kk + k) * F + col0 + n4 * 4];
        }
        __syncthreads();
#pragma unroll
        for (int k = 0; k < 16; k++) {
            int ks = kg * 16 + k;                 // this group's k within tile
            float4 b = *(const float4*)&Bs[ks * BN + tx * 4];
            unsigned long long bd[4];
            bd[0] = pack2(b.x, b.x); bd[1] = pack2(b.y, b.y);
            bd[2] = pack2(b.z, b.z); bd[3] = pack2(b.w, b.w);
            float4 a0 = *(const float4*)&As[ks * BM + ty * 8];      // (m0,m1),(m2,m3)
            float4 a1 = *(const float4*)&As[ks * BM + ty * 8 + 4];  // (m4,m5),(m6,m7)
            unsigned long long ap[4];
            ap[0] = pack2(a0.x, a0.y); ap[1] = pack2(a0.z, a0.w);
            ap[2] = pack2(a1.x, a1.y); ap[3] = pack2(a1.z, a1.w);
#pragma unroll
            for (int mp = 0; mp < 4; mp++)
#pragma unroll
                for (int n = 0; n < 4; n++) ffma2(acc[mp][n], ap[mp], bd[n]);
        }
        __syncthreads();
    }

    // ---- split-K reduction: group1 -> smem (idx-major, conflict-free),
    //      group0 adds in fixed order (group0 + group1) ----
    unsigned long long* red = (unsigned long long*)smem_buf;   // 2048 ull = 16 KB
    if (kg == 1) {
#pragma unroll
        for (int idx = 0; idx < 16; idx++)
            red[idx * 128 + wg_tid] = acc[idx >> 2][idx & 3];
    }
    __syncthreads();
    if (kg != 0) return;
#pragma unroll
    for (int idx = 0; idx < 16; idx++)
        fadd2(acc[idx >> 2][idx & 3], red[idx * 128 + wg_tid]);

    // epilogue (group0 only): unpack, store h2, fused es/ed for this head
    float as_[4], ad_[4];
#pragma unroll
    for (int n = 0; n < 4; n++) {
        as_[n] = asrc[col0 + tx * 4 + n];
        ad_[n] = adst[col0 + tx * 4 + n];
    }
    int hidx = col0 >> 6;
#pragma unroll
    for (int mp = 0; mp < 4; mp++) {
        float c0[4], c1[4];                       // rows 2mp, 2mp+1 (within ty group)
#pragma unroll
        for (int n = 0; n < 4; n++) unpack2(acc[mp][n], c0[n], c1[n]);
#pragma unroll
        for (int half = 0; half < 2; half++) {
            float* c = half ? c1 : c0;
            int gr = row0 + ty * 8 + mp * 2 + half;
            float s = c[0] * as_[0] + c[1] * as_[1] + c[2] * as_[2] + c[3] * as_[3];
            float d = c[0] * ad_[0] + c[1] * ad_[1] + c[2] * ad_[2] + c[3] * ad_[3];
#pragma unroll
            for (int off = 8; off; off >>= 1) {   // reduce across the 16 tx lanes
                s += __shfl_xor_sync(0xffffffffu, s, off);
                d += __shfl_xor_sync(0xffffffffu, d, off);
            }
            if (gr < Kn) {
                *(float4*)&g_h[gr * F + col0 + tx * 4] =
                    make_float4(c[0], c[1], c[2], c[3]);
                if (tx == 0) {
                    g_es[gr * H + hidx] = s;
                    g_ed[gr * H + hidx] = d;
                }
            }
        }
    }
}

// ---------------------------------------------------------------------------
extern "C" void kernel_launch(void* const* d_in, const int* in_sizes, int n_in,
                              void* d_out, int out_size) {
    const float* pos   = (const float*)d_in[0];
    const float* pnm   = (const float*)d_in[1];
    const float* W1    = (const float*)d_in[2];
    const float* asrc1 = (const float*)d_in[3];
    const float* adst1 = (const float*)d_in[4];
    const float* b1    = (const float*)d_in[5];
    const float* W2    = (const float*)d_in[6];
    const float* asrc2 = (const float*)d_in[7];
    const float* adst2 = (const float*)d_in[8];
    const float* b2    = (const float*)d_in[9];
    const float* fw    = (const float*)d_in[10];
    const float* fb    = (const float*)d_in[11];
    float* out = (float*)d_out;

    // zero the cell histogram via a captured memset node (replaces a kernel)
    void* cellcnt_ptr = nullptr;
    cudaGetSymbolAddress(&cellcnt_ptr, g_cellcnt);
    cudaMemsetAsync(cellcnt_ptr, 0, NCELL * sizeof(int));

    build_pts<<<(Kn + 255) / 256, 256>>>(pos, pnm);
    scan_scatter<<<1, 1024>>>();
    nbr_search<<<(Kn * 32 + 127) / 128, 128>>>();

    // ---- GAT layer 1 (scores fused into feat1) ----
    feat1<<<Kn / FNODES, F>>>(W1, asrc1, adst1);
    aggregate<false><<<(Kn * 32 + 255) / 256, 256>>>(b1, nullptr, nullptr, nullptr);

    // ---- GAT layer 2 (scores fused into gemm2 epilogue) ----
    gemm2<<<dim3(F / BN, (Kn + BM - 1) / BM), 256>>>(W2, asrc2, adst2);
    aggregate<true><<<(Mp * 32 + 255) / 256, 256>>>(b2, fw, fb, out);
}